// round 1
// baseline (speedup 1.0000x reference)
#include <cuda_runtime.h>
#include <cstdint>

// Problem shape (fixed by reference): B=2, S=2048 -> ROWS=4096, n=m=4096
#define ROWS_T 4096
#define NDIM   4096
#define MDIM   4096
#define NCODE  (MDIM * (NDIM / 8))   // 2,097,152 codewords

// Scratch (allocation-free rule: __device__ globals)
__device__ float g_Xh[(size_t)ROWS_T * NDIM];   // Hadamard-rotated input (tf32-rounded)
__device__ float g_W [(size_t)MDIM   * NDIM];   // dequantized weights (tf32-rounded)

__device__ __forceinline__ float to_tf32(float x) {
    uint32_t u;
    asm("cvt.rna.tf32.f32 %0, %1;" : "=r"(u) : "f"(x));
    return __uint_as_float(u);
}

// ---------------------------------------------------------------------------
// Kernel 1: W = grid[Qidxs].reshape(m, n), rounded to tf32
// ---------------------------------------------------------------------------
__global__ void dequant_kernel(const float* __restrict__ grid,
                               const int*   __restrict__ qidxs,
                               float*       __restrict__ W) {
    int i = blockIdx.x * blockDim.x + threadIdx.x;
    if (i >= NCODE) return;
    int idx = qidxs[i];
    const float4* g4 = reinterpret_cast<const float4*>(grid) + (size_t)idx * 2;
    float4 a = g4[0], b = g4[1];
    float4 oa = make_float4(to_tf32(a.x), to_tf32(a.y), to_tf32(a.z), to_tf32(a.w));
    float4 ob = make_float4(to_tf32(b.x), to_tf32(b.y), to_tf32(b.z), to_tf32(b.w));
    float4* o4 = reinterpret_cast<float4*>(W) + (size_t)i * 2;
    o4[0] = oa; o4[1] = ob;
}

// ---------------------------------------------------------------------------
// Kernel 2: Xh[row] = tf32( FWHT(input[row] * SU) * (1/64) )
// One block per row, 1024 threads, full row in shared memory.
// ---------------------------------------------------------------------------
__global__ void fwht_su_kernel(const float* __restrict__ in,
                               const float* __restrict__ su,
                               float*       __restrict__ out) {
    __shared__ float s[NDIM];
    const int t = threadIdx.x;                 // 0..1023
    const size_t row = blockIdx.x;
    const float4* in4 = reinterpret_cast<const float4*>(in + row * NDIM);
    const float4* su4 = reinterpret_cast<const float4*>(su);
    float4 v = in4[t];
    float4 sc = su4[t];
    s[4*t+0] = v.x * sc.x;
    s[4*t+1] = v.y * sc.y;
    s[4*t+2] = v.z * sc.z;
    s[4*t+3] = v.w * sc.w;
    __syncthreads();
    #pragma unroll
    for (int h = 1; h < NDIM; h <<= 1) {
        #pragma unroll
        for (int p = t; p < NDIM / 2; p += 1024) {
            int i = ((p & ~(h - 1)) << 1) | (p & (h - 1));
            float a = s[i], b = s[i + h];
            s[i]     = a + b;
            s[i + h] = a - b;
        }
        __syncthreads();
    }
    float4 o;
    o.x = to_tf32(s[4*t+0] * 0.015625f);
    o.y = to_tf32(s[4*t+1] * 0.015625f);
    o.z = to_tf32(s[4*t+2] * 0.015625f);
    o.w = to_tf32(s[4*t+3] * 0.015625f);
    reinterpret_cast<float4*>(out + row * NDIM)[t] = o;
}

// ---------------------------------------------------------------------------
// Kernel 4: in-place row-FWHT on GEMM output, fused with SV * (1/64)
// ---------------------------------------------------------------------------
__global__ void fwht_sv_kernel(float* __restrict__ data,
                               const float* __restrict__ sv) {
    __shared__ float s[MDIM];
    const int t = threadIdx.x;
    const size_t row = blockIdx.x;
    float4* d4 = reinterpret_cast<float4*>(data + row * MDIM);
    float4 v = d4[t];
    s[4*t+0] = v.x; s[4*t+1] = v.y; s[4*t+2] = v.z; s[4*t+3] = v.w;
    __syncthreads();
    #pragma unroll
    for (int h = 1; h < MDIM; h <<= 1) {
        #pragma unroll
        for (int p = t; p < MDIM / 2; p += 1024) {
            int i = ((p & ~(h - 1)) << 1) | (p & (h - 1));
            float a = s[i], b = s[i + h];
            s[i]     = a + b;
            s[i + h] = a - b;
        }
        __syncthreads();
    }
    const float4* sv4 = reinterpret_cast<const float4*>(sv);
    float4 sc = sv4[t];
    float4 o;
    o.x = s[4*t+0] * sc.x * 0.015625f;
    o.y = s[4*t+1] * sc.y * 0.015625f;
    o.z = s[4*t+2] * sc.z * 0.015625f;
    o.w = s[4*t+3] * sc.w * 0.015625f;
    d4[t] = o;
}

// ---------------------------------------------------------------------------
// Kernel 3: C[i,j] = sum_k Xh[i,k] * W[j,k]   (NT GEMM, tf32 MMA, fp32 accum)
// Tile 128x128x32; 8 warps (2 along M x 4 along N), warp tile 64x32.
// mma.sync.m16n8k8: 4 m-tiles x 4 n-tiles per warp per k-step.
// ---------------------------------------------------------------------------
#define BKg  32
#define PADg 36   // 36 floats/row: keeps 16B alignment AND conflict-free frag reads

__global__ __launch_bounds__(256, 1)
void gemm_tf32_kernel(const float* __restrict__ A,
                      const float* __restrict__ B,
                      float*       __restrict__ C) {
    __shared__ float As[128 * PADg];
    __shared__ float Bs[128 * PADg];

    const int tid   = threadIdx.x;
    const int warpId = tid >> 5;
    const int lane  = tid & 31;
    const int g     = lane >> 2;      // 0..7
    const int t4    = lane & 3;       // 0..3
    const int wm    = (warpId & 1) * 64;   // warp M offset
    const int wn    = (warpId >> 1) * 32;  // warp N offset

    const int ldr = tid >> 3;         // 0..31  (row within 32-row chunk)
    const int ldc = (tid & 7) * 4;    // 0,4,...,28

    const float* Ag = A + (size_t)(blockIdx.y * 128 + ldr) * NDIM + ldc;
    const float* Bg = B + (size_t)(blockIdx.x * 128 + ldr) * NDIM + ldc;

    float4 ra[4], rb[4];
    float c[4][4][4];
    #pragma unroll
    for (int i = 0; i < 4; i++)
        #pragma unroll
        for (int j = 0; j < 4; j++)
            #pragma unroll
            for (int k = 0; k < 4; k++) c[i][j][k] = 0.f;

    // prologue: load k-tile 0 into smem
    #pragma unroll
    for (int i = 0; i < 4; i++) {
        ra[i] = *reinterpret_cast<const float4*>(Ag + (size_t)(i * 32) * NDIM);
        rb[i] = *reinterpret_cast<const float4*>(Bg + (size_t)(i * 32) * NDIM);
    }
    #pragma unroll
    for (int i = 0; i < 4; i++) {
        *reinterpret_cast<float4*>(&As[(ldr + i * 32) * PADg + ldc]) = ra[i];
        *reinterpret_cast<float4*>(&Bs[(ldr + i * 32) * PADg + ldc]) = rb[i];
    }
    __syncthreads();

    const int KT = NDIM / BKg;  // 128
    for (int kt = 1; kt <= KT; kt++) {
        // prefetch next tile into registers while computing current
        if (kt < KT) {
            const float* Agk = Ag + kt * BKg;
            const float* Bgk = Bg + kt * BKg;
            #pragma unroll
            for (int i = 0; i < 4; i++) {
                ra[i] = *reinterpret_cast<const float4*>(Agk + (size_t)(i * 32) * NDIM);
                rb[i] = *reinterpret_cast<const float4*>(Bgk + (size_t)(i * 32) * NDIM);
            }
        }

        #pragma unroll
        for (int ks = 0; ks < 4; ks++) {
            const int k0 = ks * 8;
            uint32_t af[4][4], bf[4][2];
            #pragma unroll
            for (int mi = 0; mi < 4; mi++) {
                const int m = wm + mi * 16;
                af[mi][0] = __float_as_uint(As[(m + g    ) * PADg + k0 + t4    ]);
                af[mi][1] = __float_as_uint(As[(m + g + 8) * PADg + k0 + t4    ]);
                af[mi][2] = __float_as_uint(As[(m + g    ) * PADg + k0 + t4 + 4]);
                af[mi][3] = __float_as_uint(As[(m + g + 8) * PADg + k0 + t4 + 4]);
            }
            #pragma unroll
            for (int ni = 0; ni < 4; ni++) {
                const int n = wn + ni * 8;
                bf[ni][0] = __float_as_uint(Bs[(n + g) * PADg + k0 + t4    ]);
                bf[ni][1] = __float_as_uint(Bs[(n + g) * PADg + k0 + t4 + 4]);
            }
            #pragma unroll
            for (int mi = 0; mi < 4; mi++)
                #pragma unroll
                for (int ni = 0; ni < 4; ni++) {
                    asm volatile(
                        "mma.sync.aligned.m16n8k8.row.col.f32.tf32.tf32.f32 "
                        "{%0,%1,%2,%3}, {%4,%5,%6,%7}, {%8,%9}, {%0,%1,%2,%3};\n"
                        : "+f"(c[mi][ni][0]), "+f"(c[mi][ni][1]),
                          "+f"(c[mi][ni][2]), "+f"(c[mi][ni][3])
                        : "r"(af[mi][0]), "r"(af[mi][1]), "r"(af[mi][2]), "r"(af[mi][3]),
                          "r"(bf[ni][0]), "r"(bf[ni][1]));
                }
        }
        __syncthreads();
        if (kt < KT) {
            #pragma unroll
            for (int i = 0; i < 4; i++) {
                *reinterpret_cast<float4*>(&As[(ldr + i * 32) * PADg + ldc]) = ra[i];
                *reinterpret_cast<float4*>(&Bs[(ldr + i * 32) * PADg + ldc]) = rb[i];
            }
            __syncthreads();
        }
    }

    // epilogue: c0,c1 -> (row g, cols 2t4,2t4+1); c2,c3 -> (row g+8, same cols)
    float* Cb = C + (size_t)(blockIdx.y * 128 + wm) * MDIM + blockIdx.x * 128 + wn;
    #pragma unroll
    for (int mi = 0; mi < 4; mi++) {
        #pragma unroll
        for (int ni = 0; ni < 4; ni++) {
            const int col = ni * 8 + 2 * t4;
            float2 v0 = make_float2(c[mi][ni][0], c[mi][ni][1]);
            float2 v1 = make_float2(c[mi][ni][2], c[mi][ni][3]);
            *reinterpret_cast<float2*>(Cb + (size_t)(mi * 16 + g    ) * MDIM + col) = v0;
            *reinterpret_cast<float2*>(Cb + (size_t)(mi * 16 + g + 8) * MDIM + col) = v1;
        }
    }
}

// ---------------------------------------------------------------------------
// Launch: input, SU, SV, grid, Qidxs (metadata order)
// ---------------------------------------------------------------------------
extern "C" void kernel_launch(void* const* d_in, const int* in_sizes, int n_in,
                              void* d_out, int out_size) {
    const float* input = (const float*)d_in[0];
    const float* SU    = (const float*)d_in[1];
    const float* SV    = (const float*)d_in[2];
    const float* grid  = (const float*)d_in[3];
    const int*   qidxs = (const int*)  d_in[4];
    float* out = (float*)d_out;

    float* Xh = nullptr;
    float* W  = nullptr;
    cudaGetSymbolAddress((void**)&Xh, g_Xh);
    cudaGetSymbolAddress((void**)&W,  g_W);

    // 1. dequantize codebook -> W (tf32-rounded)
    dequant_kernel<<<(NCODE + 255) / 256, 256>>>(grid, qidxs, W);

    // 2. Xh = tf32( FWHT(input * SU) / 64 )
    fwht_su_kernel<<<ROWS_T, 1024>>>(input, SU, Xh);

    // 3. out = Xh @ W^T  (tf32 MMA, fp32 accumulate)
    dim3 gdim(MDIM / 128, ROWS_T / 128);
    gemm_tf32_kernel<<<gdim, 256>>>(Xh, W, out);

    // 4. out = FWHT(out) * SV / 64   (in place)
    fwht_sv_kernel<<<ROWS_T, 1024>>>(out, SV);
}